// round 1
// baseline (speedup 1.0000x reference)
#include <cuda_runtime.h>

// Problem constants
#define S_  2048
#define B_  2
#define E_  1024
#define H_  16
#define D_  64
#define T_  2048
#define MB_ 4096          // S*B rows

// ---------------------------------------------------------------------------
// Scratch (no allocations allowed -> __device__ globals)
// ---------------------------------------------------------------------------
__device__ float g_q [4096L * 1024];                  // (row=2s+b, h*64+d)
__device__ float g_k [4096L * 1024];
__device__ float g_v [4096L * 1024];
__device__ float g_o [4096L * 1024];                  // attention output, same layout
__device__ float g_sc[2048L * 2 * 16 * 2048];         // scores (s,b,h,t)  = 512 MB

// ---------------------------------------------------------------------------
// NT GEMM: C[m,n] = alpha * sum_k A[m,k]*B[n,k]  (+ bias[n])
// Tiles: 128x128x8, 256 threads, 8x8 per-thread microtile.
// M,N implied by grid (y = M/128, x = N/128, z = batch). K % 8 == 0.
// ---------------------------------------------------------------------------
__global__ __launch_bounds__(256)
void gemm_nt(const float* __restrict__ A, const float* __restrict__ Bm,
             const float* __restrict__ bias, float* __restrict__ C,
             int K, long lda, long ldb, long ldc,
             long bsA, long bsB, long bsC, float alpha)
{
    __shared__ float As[8][128];
    __shared__ float Bs[8][128];

    const int  tid = threadIdx.x;
    const long bm = blockIdx.y, bn = blockIdx.x, bz = blockIdx.z;

    A  += bz * bsA + bm * 128 * lda;
    Bm += bz * bsB + bn * 128 * ldb;
    C  += bz * bsC + bm * 128 * ldc + bn * 128;

    // loader: 256 threads x 1 float4 = 128 rows x 8 k-floats
    const int lr = tid >> 1;
    const int lc = (tid & 1) * 4;
    // compute mapping: 16x16 thread grid, 8x8 microtile
    const int trow = (tid >> 4) * 8;
    const int tcol = (tid & 15) * 8;

    float acc[8][8];
#pragma unroll
    for (int i = 0; i < 8; i++)
#pragma unroll
        for (int j = 0; j < 8; j++) acc[i][j] = 0.0f;

    for (int k0 = 0; k0 < K; k0 += 8) {
        float4 av = *(const float4*)(A  + (long)lr * lda + k0 + lc);
        float4 bv = *(const float4*)(Bm + (long)lr * ldb + k0 + lc);
        As[lc + 0][lr] = av.x; As[lc + 1][lr] = av.y;
        As[lc + 2][lr] = av.z; As[lc + 3][lr] = av.w;
        Bs[lc + 0][lr] = bv.x; Bs[lc + 1][lr] = bv.y;
        Bs[lc + 2][lr] = bv.z; Bs[lc + 3][lr] = bv.w;
        __syncthreads();

#pragma unroll
        for (int kk = 0; kk < 8; kk++) {
            float ra[8], rb[8];
            *(float4*)(ra    ) = *(const float4*)&As[kk][trow    ];
            *(float4*)(ra + 4) = *(const float4*)&As[kk][trow + 4];
            *(float4*)(rb    ) = *(const float4*)&Bs[kk][tcol    ];
            *(float4*)(rb + 4) = *(const float4*)&Bs[kk][tcol + 4];
#pragma unroll
            for (int i = 0; i < 8; i++)
#pragma unroll
                for (int j = 0; j < 8; j++)
                    acc[i][j] += ra[i] * rb[j];
        }
        __syncthreads();
    }

    float bvreg[8];
#pragma unroll
    for (int j = 0; j < 8; j++)
        bvreg[j] = bias ? bias[bn * 128 + tcol + j] : 0.0f;

#pragma unroll
    for (int i = 0; i < 8; i++) {
        float4 o0, o1;
        o0.x = acc[i][0] * alpha + bvreg[0];
        o0.y = acc[i][1] * alpha + bvreg[1];
        o0.z = acc[i][2] * alpha + bvreg[2];
        o0.w = acc[i][3] * alpha + bvreg[3];
        o1.x = acc[i][4] * alpha + bvreg[4];
        o1.y = acc[i][5] * alpha + bvreg[5];
        o1.z = acc[i][6] * alpha + bvreg[6];
        o1.w = acc[i][7] * alpha + bvreg[7];
        *(float4*)(C + (long)(trow + i) * ldc + tcol    ) = o0;
        *(float4*)(C + (long)(trow + i) * ldc + tcol + 4) = o1;
    }
}

// ---------------------------------------------------------------------------
// NN GEMM (for attn @ V): C[m,n] = sum_k A[m,k]*B[k,n]
// Tiles: 128x64x16, 256 threads, 8x4 microtile. N == 64 (one n-tile).
// ---------------------------------------------------------------------------
__global__ __launch_bounds__(256)
void gemm_nn(const float* __restrict__ A, const float* __restrict__ Bm,
             float* __restrict__ C, int K,
             long lda, long ldb, long ldc,
             long bsA, long bsB, long bsC)
{
    __shared__ float As[16][128];
    __shared__ float Bs[16][64];

    const int  tid = threadIdx.x;
    const long bm = blockIdx.y, bz = blockIdx.z;

    A  += bz * bsA + bm * 128 * lda;
    Bm += bz * bsB;
    C  += bz * bsC + bm * 128 * ldc;

    // A loader: 128x16 floats = 512 float4 -> 2 per thread (rows r, r+64)
    const int arow = tid >> 2;
    const int akc  = (tid & 3) * 4;
    // B loader: 16x64 floats = 256 float4 -> 1 per thread
    const int brow = tid >> 4;
    const int bcol = (tid & 15) * 4;
    // compute mapping: 16x16 grid, 8x4 microtile
    const int trow = (tid >> 4) * 8;
    const int tcol = (tid & 15) * 4;

    float acc[8][4];
#pragma unroll
    for (int i = 0; i < 8; i++)
#pragma unroll
        for (int j = 0; j < 4; j++) acc[i][j] = 0.0f;

    for (int k0 = 0; k0 < K; k0 += 16) {
        float4 a0 = *(const float4*)(A + (long)arow        * lda + k0 + akc);
        float4 a1 = *(const float4*)(A + (long)(arow + 64) * lda + k0 + akc);
        float4 b0 = *(const float4*)(Bm + (long)(k0 + brow) * ldb + bcol);
        As[akc + 0][arow] = a0.x; As[akc + 1][arow] = a0.y;
        As[akc + 2][arow] = a0.z; As[akc + 3][arow] = a0.w;
        As[akc + 0][arow + 64] = a1.x; As[akc + 1][arow + 64] = a1.y;
        As[akc + 2][arow + 64] = a1.z; As[akc + 3][arow + 64] = a1.w;
        *(float4*)&Bs[brow][bcol] = b0;
        __syncthreads();

#pragma unroll
        for (int kk = 0; kk < 16; kk++) {
            float ra[8], rb[4];
            *(float4*)(ra    ) = *(const float4*)&As[kk][trow    ];
            *(float4*)(ra + 4) = *(const float4*)&As[kk][trow + 4];
            *(float4*)(rb    ) = *(const float4*)&Bs[kk][tcol    ];
#pragma unroll
            for (int i = 0; i < 8; i++)
#pragma unroll
                for (int j = 0; j < 4; j++)
                    acc[i][j] += ra[i] * rb[j];
        }
        __syncthreads();
    }

#pragma unroll
    for (int i = 0; i < 8; i++) {
        float4 o0;
        o0.x = acc[i][0]; o0.y = acc[i][1]; o0.z = acc[i][2]; o0.w = acc[i][3];
        *(float4*)(C + (long)(trow + i) * ldc + tcol) = o0;
    }
}

// ---------------------------------------------------------------------------
// Softmax over the HEAD axis (axis 2 of (s,b,h,t)) -- local per (s,b,t).
// In-place on g_sc. Fully coalesced: thread index maps t fastest.
// ---------------------------------------------------------------------------
__global__ __launch_bounds__(256)
void softmax_h(float* __restrict__ p)
{
    long idx = (long)blockIdx.x * blockDim.x + threadIdx.x;
    const long total = (long)S_ * B_ * T_;
    if (idx >= total) return;

    int  t = (int)(idx % T_);
    long r = idx / T_;
    int  b = (int)(r % B_);
    long s = r / B_;
    long base = ((s * B_ + b) * (long)H_) * T_ + t;

    float v[H_];
    float m = -1e30f;
#pragma unroll
    for (int h = 0; h < H_; h++) {
        v[h] = p[base + (long)h * T_];
        m = fmaxf(m, v[h]);
    }
    float sum = 0.0f;
#pragma unroll
    for (int h = 0; h < H_; h++) {
        v[h] = expf(v[h] - m);
        sum += v[h];
    }
    float inv = 1.0f / sum;
#pragma unroll
    for (int h = 0; h < H_; h++)
        p[base + (long)h * T_] = v[h] * inv;
}

// ---------------------------------------------------------------------------
// Launch
// ---------------------------------------------------------------------------
extern "C" void kernel_launch(void* const* d_in, const int* in_sizes, int n_in,
                              void* d_out, int out_size)
{
    const float* x  = (const float*)d_in[0];
    const float* Wq = (const float*)d_in[1];
    const float* bq = (const float*)d_in[2];
    const float* Wk = (const float*)d_in[3];
    const float* bk = (const float*)d_in[4];
    const float* Wv = (const float*)d_in[5];
    const float* bv = (const float*)d_in[6];
    const float* Wo = (const float*)d_in[7];
    const float* bo = (const float*)d_in[8];
    float* out = (float*)d_out;

    float *q, *k, *v, *o, *sc;
    cudaGetSymbolAddress((void**)&q,  g_q);
    cudaGetSymbolAddress((void**)&k,  g_k);
    cudaGetSymbolAddress((void**)&v,  g_v);
    cudaGetSymbolAddress((void**)&o,  g_o);
    cudaGetSymbolAddress((void**)&sc, g_sc);

    dim3 blk(256);

    // 1-3. Q/K/V projections: (4096x1024) = x(4096x1024) @ W^T + b
    gemm_nt<<<dim3(8, 32, 1), blk>>>(x, Wq, bq, q, 1024, 1024, 1024, 1024, 0, 0, 0, 1.0f);
    gemm_nt<<<dim3(8, 32, 1), blk>>>(x, Wk, bk, k, 1024, 1024, 1024, 1024, 0, 0, 0, 1.0f);
    gemm_nt<<<dim3(8, 32, 1), blk>>>(x, Wv, bv, v, 1024, 1024, 1024, 1024, 0, 0, 0, 1.0f);

    // 4. scores[s,b,h,t] = (1/8) * sum_d Q[s,(b,h),d] * K[t,(b,h),d]
    //    batch z = b*H + h: Q/K base z*64 (lda/ldb = 2048), C base z*2048 (ldc = 65536)
    gemm_nt<<<dim3(16, 16, 32), blk>>>(q, k, nullptr, sc, 64,
                                       2048, 2048, 65536,
                                       64, 64, 2048, 0.125f);

    // 5. softmax over heads (axis 2), in place
    softmax_h<<<32768, 256>>>(sc);

    // 6. O[s,(b,h),d] = sum_t attn[s,(b,h),t] * V[t,(b,h),d]
    gemm_nn<<<dim3(1, 16, 32), blk>>>(sc, v, o, 2048,
                                      65536, 2048, 2048,
                                      2048, 64, 64);

    // 7. out = O(4096x1024) @ Wo^T + bo
    gemm_nt<<<dim3(8, 32, 1), blk>>>(o, Wo, bo, out, 1024, 1024, 1024, 1024, 0, 0, 0, 1.0f);
}

// round 4
// speedup vs baseline: 1.6601x; 1.6601x over previous
#include <cuda_runtime.h>
#include <cuda_bf16.h>
#include <cstdint>

// Problem constants
#define S_  2048
#define B_  2
#define E_  1024
#define H_  16
#define D_  64
#define T_  2048

// ---------------------------------------------------------------------------
// Scratch (no allocations allowed -> __device__ globals)
// ---------------------------------------------------------------------------
__device__ float g_q [4096L * 1024];                  // (row=2s+b, h*64+d)
__device__ float g_k [4096L * 1024];
__device__ float g_v [4096L * 1024];
__device__ float g_o [4096L * 1024];
__device__ float g_sc[2048L * 2 * 16 * 2048];         // scores (s,b,h,t)

// ---------------------------------------------------------------------------
// Warp-level bf16 MMA (portable sm_80+ ISA, works on base sm_100)
// D(16x8,f32) += A(16x16,bf16,row) * B(16x8,bf16,col)
// ---------------------------------------------------------------------------
__device__ __forceinline__ void mma16816(float* c, uint32_t a0, uint32_t a1,
                                         uint32_t a2, uint32_t a3,
                                         uint32_t b0, uint32_t b1)
{
    asm volatile(
        "mma.sync.aligned.m16n8k16.row.col.f32.bf16.bf16.f32 "
        "{%0,%1,%2,%3}, {%4,%5,%6,%7}, {%8,%9}, {%0,%1,%2,%3};"
        : "+f"(c[0]), "+f"(c[1]), "+f"(c[2]), "+f"(c[3])
        : "r"(a0), "r"(a1), "r"(a2), "r"(a3), "r"(b0), "r"(b1));
}

// ---------------------------------------------------------------------------
// NT GEMM body, split-bf16 fp32 emulation via mma.sync.
// C[m,n] = alpha * sum_k A[m,k]*B[n,k] (+ bias[n]); A,B,C,bias pre-offset.
// CTA tile 128x128, K-chunks of 32. 256 threads = 8 warps (2m x 4n),
// warp tile 64x32 = 4x4 mma tiles of m16n8.
// ---------------------------------------------------------------------------
#define KC    32
#define KPAD  40    // elements; 80B row stride -> conflict-free frag loads

__device__ __forceinline__ void gemm_body(const float* __restrict__ A,
                                          const float* __restrict__ Bm,
                                          const float* __restrict__ bias,
                                          float* __restrict__ C,
                                          int K, long lda, long ldb, long ldc,
                                          float alpha)
{
    __shared__ __nv_bfloat16 Ahi[128 * KPAD];
    __shared__ __nv_bfloat16 Alo[128 * KPAD];
    __shared__ __nv_bfloat16 Bhi[128 * KPAD];
    __shared__ __nv_bfloat16 Blo[128 * KPAD];

    const int tid  = threadIdx.x;
    const int wid  = tid >> 5;
    const int lane = tid & 31;
    const int wm   = (wid >> 2) * 64;       // warp m offset (0 or 64)
    const int wn   = (wid & 3) * 32;        // warp n offset (0..96)
    const int lrow = lane >> 2;             // 0..7
    const int lk2  = (lane & 3) * 2;        // 0,2,4,6

    float acc[4][4][4];
#pragma unroll
    for (int i = 0; i < 4; i++)
#pragma unroll
        for (int j = 0; j < 4; j++)
#pragma unroll
            for (int r = 0; r < 4; r++) acc[i][j][r] = 0.0f;

    for (int k0 = 0; k0 < K; k0 += KC) {
        // ---- stage A and B chunk (128 rows x 32 k) as bf16 hi/lo ----
        // 1024 float4 per matrix; 256 threads x 4 iterations.
#pragma unroll
        for (int i = 0; i < 4; i++) {
            int idx4 = tid + i * 256;
            int row  = idx4 >> 3;            // 8 float4 per row
            int colf = (idx4 & 7) * 4;       // 0..28
            // A
            {
                float4 vv = *(const float4*)(A + (long)row * lda + k0 + colf);
                __nv_bfloat16 h0 = __float2bfloat16(vv.x), h1 = __float2bfloat16(vv.y),
                              h2 = __float2bfloat16(vv.z), h3 = __float2bfloat16(vv.w);
                __nv_bfloat16 l0 = __float2bfloat16(vv.x - __bfloat162float(h0));
                __nv_bfloat16 l1 = __float2bfloat16(vv.y - __bfloat162float(h1));
                __nv_bfloat16 l2 = __float2bfloat16(vv.z - __bfloat162float(h2));
                __nv_bfloat16 l3 = __float2bfloat16(vv.w - __bfloat162float(h3));
                uint2 hh = make_uint2(
                    ((uint32_t)__bfloat16_as_ushort(h1) << 16) | __bfloat16_as_ushort(h0),
                    ((uint32_t)__bfloat16_as_ushort(h3) << 16) | __bfloat16_as_ushort(h2));
                uint2 ll = make_uint2(
                    ((uint32_t)__bfloat16_as_ushort(l1) << 16) | __bfloat16_as_ushort(l0),
                    ((uint32_t)__bfloat16_as_ushort(l3) << 16) | __bfloat16_as_ushort(l2));
                *(uint2*)&Ahi[row * KPAD + colf] = hh;
                *(uint2*)&Alo[row * KPAD + colf] = ll;
            }
            // B
            {
                float4 vv = *(const float4*)(Bm + (long)row * ldb + k0 + colf);
                __nv_bfloat16 h0 = __float2bfloat16(vv.x), h1 = __float2bfloat16(vv.y),
                              h2 = __float2bfloat16(vv.z), h3 = __float2bfloat16(vv.w);
                __nv_bfloat16 l0 = __float2bfloat16(vv.x - __bfloat162float(h0));
                __nv_bfloat16 l1 = __float2bfloat16(vv.y - __bfloat162float(h1));
                __nv_bfloat16 l2 = __float2bfloat16(vv.z - __bfloat162float(h2));
                __nv_bfloat16 l3 = __float2bfloat16(vv.w - __bfloat162float(h3));
                uint2 hh = make_uint2(
                    ((uint32_t)__bfloat16_as_ushort(h1) << 16) | __bfloat16_as_ushort(h0),
                    ((uint32_t)__bfloat16_as_ushort(h3) << 16) | __bfloat16_as_ushort(h2));
                uint2 ll = make_uint2(
                    ((uint32_t)__bfloat16_as_ushort(l1) << 16) | __bfloat16_as_ushort(l0),
                    ((uint32_t)__bfloat16_as_ushort(l3) << 16) | __bfloat16_as_ushort(l2));
                *(uint2*)&Bhi[row * KPAD + colf] = hh;
                *(uint2*)&Blo[row * KPAD + colf] = ll;
            }
        }
        __syncthreads();

        // ---- compute: 2 k-steps of 16 per chunk ----
#pragma unroll
        for (int kc = 0; kc < KC; kc += 16) {
            // B fragments for 4 n-tiles (hi & lo)
            uint32_t bh[4][2], bl[4][2];
#pragma unroll
            for (int nt = 0; nt < 4; nt++) {
                int nrow = wn + nt * 8 + lrow;
                int kk   = kc + lk2;
                bh[nt][0] = *(const uint32_t*)&Bhi[nrow * KPAD + kk];
                bh[nt][1] = *(const uint32_t*)&Bhi[nrow * KPAD + kk + 8];
                bl[nt][0] = *(const uint32_t*)&Blo[nrow * KPAD + kk];
                bl[nt][1] = *(const uint32_t*)&Blo[nrow * KPAD + kk + 8];
            }
#pragma unroll
            for (int mt = 0; mt < 4; mt++) {
                int mrow = wm + mt * 16 + lrow;
                int kk   = kc + lk2;
                uint32_t ah0 = *(const uint32_t*)&Ahi[mrow * KPAD + kk];
                uint32_t ah1 = *(const uint32_t*)&Ahi[(mrow + 8) * KPAD + kk];
                uint32_t ah2 = *(const uint32_t*)&Ahi[mrow * KPAD + kk + 8];
                uint32_t ah3 = *(const uint32_t*)&Ahi[(mrow + 8) * KPAD + kk + 8];
                uint32_t al0 = *(const uint32_t*)&Alo[mrow * KPAD + kk];
                uint32_t al1 = *(const uint32_t*)&Alo[(mrow + 8) * KPAD + kk];
                uint32_t al2 = *(const uint32_t*)&Alo[mrow * KPAD + kk + 8];
                uint32_t al3 = *(const uint32_t*)&Alo[(mrow + 8) * KPAD + kk + 8];
#pragma unroll
                for (int nt = 0; nt < 4; nt++) {
                    mma16816(acc[mt][nt], ah0, ah1, ah2, ah3, bh[nt][0], bh[nt][1]);
                    mma16816(acc[mt][nt], ah0, ah1, ah2, ah3, bl[nt][0], bl[nt][1]);
                    mma16816(acc[mt][nt], al0, al1, al2, al3, bh[nt][0], bh[nt][1]);
                }
            }
        }
        __syncthreads();
    }

    // ---- epilogue ----
#pragma unroll
    for (int mt = 0; mt < 4; mt++) {
        int row = wm + mt * 16 + lrow;
#pragma unroll
        for (int nt = 0; nt < 4; nt++) {
            int col = wn + nt * 8 + (lane & 3) * 2;
            float b0 = 0.f, b1 = 0.f;
            if (bias) { b0 = bias[col]; b1 = bias[col + 1]; }
            float2 o0, o1;
            o0.x = acc[mt][nt][0] * alpha + b0;
            o0.y = acc[mt][nt][1] * alpha + b1;
            o1.x = acc[mt][nt][2] * alpha + b0;
            o1.y = acc[mt][nt][3] * alpha + b1;
            *(float2*)(C + (long)row * ldc + col)       = o0;
            *(float2*)(C + (long)(row + 8) * ldc + col) = o1;
        }
    }
}

// ---------------------------------------------------------------------------
// Wrapper kernels
// ---------------------------------------------------------------------------
// Fused Q/K/V projection: grid (8, 32, 3), z selects matrix.
__global__ __launch_bounds__(256)
void gemm_qkv(const float* __restrict__ x,
              const float* __restrict__ Wq, const float* __restrict__ bq, float* q,
              const float* __restrict__ Wk, const float* __restrict__ bk, float* k,
              const float* __restrict__ Wv, const float* __restrict__ bv, float* v)
{
    const long bm = blockIdx.y, bn = blockIdx.x;
    const int  z  = blockIdx.z;
    const float* W = (z == 0) ? Wq : (z == 1) ? Wk : Wv;
    const float* b = (z == 0) ? bq : (z == 1) ? bk : bv;
    float*       C = (z == 0) ? q  : (z == 1) ? k  : v;
    gemm_body(x + bm * 128 * 1024,
              W + bn * 128 * 1024,
              b + bn * 128,
              C + bm * 128 * 1024 + bn * 128,
              1024, 1024, 1024, 1024, 1.0f);
}

// Out projection: grid (8, 32, 1).
__global__ __launch_bounds__(256)
void gemm_proj(const float* __restrict__ A, const float* __restrict__ W,
               const float* __restrict__ bias, float* __restrict__ C)
{
    const long bm = blockIdx.y, bn = blockIdx.x;
    gemm_body(A + bm * 128 * 1024,
              W + bn * 128 * 1024,
              bias + bn * 128,
              C + bm * 128 * 1024 + bn * 128,
              1024, 1024, 1024, 1024, 1.0f);
}

// Scores: grid (16, 16, 32), z = b*H + h. K=64.
__global__ __launch_bounds__(256)
void gemm_sc(const float* __restrict__ q, const float* __restrict__ k,
             float* __restrict__ sc)
{
    const long bm = blockIdx.y, bn = blockIdx.x, bz = blockIdx.z;
    gemm_body(q  + bz * 64   + bm * 128 * 2048,
              k  + bz * 64   + bn * 128 * 2048,
              nullptr,
              sc + bz * 2048 + bm * 128 * 65536 + bn * 128,
              64, 2048, 2048, 65536, 0.125f);
}

// ---------------------------------------------------------------------------
// NN GEMM (attn @ V), SIMT fp32 (known correct from R1)
// ---------------------------------------------------------------------------
__global__ __launch_bounds__(256)
void gemm_nn(const float* __restrict__ A, const float* __restrict__ Bm,
             float* __restrict__ C, int K,
             long lda, long ldb, long ldc,
             long bsA, long bsB, long bsC)
{
    __shared__ float As[16][128];
    __shared__ float Bs[16][64];

    const int  tid = threadIdx.x;
    const long bm = blockIdx.y, bz = blockIdx.z;

    A  += bz * bsA + bm * 128 * lda;
    Bm += bz * bsB;
    C  += bz * bsC + bm * 128 * ldc;

    const int arow = tid >> 2;
    const int akc  = (tid & 3) * 4;
    const int brow = tid >> 4;
    const int bcol = (tid & 15) * 4;
    const int trow = (tid >> 4) * 8;
    const int tcol = (tid & 15) * 4;

    float acc[8][4];
#pragma unroll
    for (int i = 0; i < 8; i++)
#pragma unroll
        for (int j = 0; j < 4; j++) acc[i][j] = 0.0f;

    for (int k0 = 0; k0 < K; k0 += 16) {
        float4 a0 = *(const float4*)(A + (long)arow        * lda + k0 + akc);
        float4 a1 = *(const float4*)(A + (long)(arow + 64) * lda + k0 + akc);
        float4 b0 = *(const float4*)(Bm + (long)(k0 + brow) * ldb + bcol);
        As[akc + 0][arow] = a0.x; As[akc + 1][arow] = a0.y;
        As[akc + 2][arow] = a0.z; As[akc + 3][arow] = a0.w;
        As[akc + 0][arow + 64] = a1.x; As[akc + 1][arow + 64] = a1.y;
        As[akc + 2][arow + 64] = a1.z; As[akc + 3][arow + 64] = a1.w;
        *(float4*)&Bs[brow][bcol] = b0;
        __syncthreads();

#pragma unroll
        for (int kk = 0; kk < 16; kk++) {
            float ra[8], rb[4];
            *(float4*)(ra    ) = *(const float4*)&As[kk][trow    ];
            *(float4*)(ra + 4) = *(const float4*)&As[kk][trow + 4];
            *(float4*)(rb    ) = *(const float4*)&Bs[kk][tcol    ];
#pragma unroll
            for (int i = 0; i < 8; i++)
#pragma unroll
                for (int j = 0; j < 4; j++)
                    acc[i][j] += ra[i] * rb[j];
        }
        __syncthreads();
    }

#pragma unroll
    for (int i = 0; i < 8; i++) {
        float4 o0;
        o0.x = acc[i][0]; o0.y = acc[i][1]; o0.z = acc[i][2]; o0.w = acc[i][3];
        *(float4*)(C + (long)(trow + i) * ldc + tcol) = o0;
    }
}

// ---------------------------------------------------------------------------
// Softmax over the HEAD axis (known correct from R1)
// ---------------------------------------------------------------------------
__global__ __launch_bounds__(256)
void softmax_h(float* __restrict__ p)
{
    long idx = (long)blockIdx.x * blockDim.x + threadIdx.x;
    const long total = (long)S_ * B_ * T_;
    if (idx >= total) return;

    int  t = (int)(idx % T_);
    long r = idx / T_;
    int  b = (int)(r % B_);
    long s = r / B_;
    long base = ((s * B_ + b) * (long)H_) * T_ + t;

    float v[H_];
    float m = -1e30f;
#pragma unroll
    for (int h = 0; h < H_; h++) {
        v[h] = p[base + (long)h * T_];
        m = fmaxf(m, v[h]);
    }
    float sum = 0.0f;
#pragma unroll
    for (int h = 0; h < H_; h++) {
        v[h] = expf(v[h] - m);
        sum += v[h];
    }
    float inv = 1.0f / sum;
#pragma unroll
    for (int h = 0; h < H_; h++)
        p[base + (long)h * T_] = v[h] * inv;
}

// ---------------------------------------------------------------------------
// Launch
// ---------------------------------------------------------------------------
extern "C" void kernel_launch(void* const* d_in, const int* in_sizes, int n_in,
                              void* d_out, int out_size)
{
    const float* x  = (const float*)d_in[0];
    const float* Wq = (const float*)d_in[1];
    const float* bq = (const float*)d_in[2];
    const float* Wk = (const float*)d_in[3];
    const float* bk = (const float*)d_in[4];
    const float* Wv = (const float*)d_in[5];
    const float* bv = (const float*)d_in[6];
    const float* Wo = (const float*)d_in[7];
    const float* bo = (const float*)d_in[8];
    float* out = (float*)d_out;

    float *q, *k, *v, *o, *sc;
    cudaGetSymbolAddress((void**)&q,  g_q);
    cudaGetSymbolAddress((void**)&k,  g_k);
    cudaGetSymbolAddress((void**)&v,  g_v);
    cudaGetSymbolAddress((void**)&o,  g_o);
    cudaGetSymbolAddress((void**)&sc, g_sc);

    // 1. Fused Q/K/V projections (mma.sync split-bf16)
    gemm_qkv<<<dim3(8, 32, 3), 256>>>(x, Wq, bq, q, Wk, bk, k, Wv, bv, v);

    // 2. scores (mma.sync split-bf16), batch z = b*H + h
    gemm_sc<<<dim3(16, 16, 32), 256>>>(q, k, sc);

    // 3. softmax over heads (axis 2), in place
    softmax_h<<<32768, 256>>>(sc);

    // 4. O = attn @ V (SIMT)
    gemm_nn<<<dim3(1, 16, 32), 256>>>(sc, v, o, 2048,
                                      65536, 2048, 2048,
                                      2048, 64, 64);

    // 5. out projection (mma.sync split-bf16)
    gemm_proj<<<dim3(8, 32, 1), 256>>>(o, Wo, bo, out);
}

// round 7
// speedup vs baseline: 1.7894x; 1.0778x over previous
#include <cuda_runtime.h>
#include <cuda_bf16.h>
#include <cstdint>

typedef __nv_bfloat16 bf16;

// Problem constants
#define S_  2048
#define B_  2
#define E_  1024
#define H_  16
#define D_  64
#define T_  2048

// ---------------------------------------------------------------------------
// Scratch (__device__ globals; no allocations allowed)
// ---------------------------------------------------------------------------
__device__ bf16 g_xh [4096L * 1024], g_xl [4096L * 1024];
__device__ bf16 g_wqh[1024L * 1024], g_wql[1024L * 1024];
__device__ bf16 g_wkh[1024L * 1024], g_wkl[1024L * 1024];
__device__ bf16 g_wvh[1024L * 1024], g_wvl[1024L * 1024];
__device__ bf16 g_woh[1024L * 1024], g_wol[1024L * 1024];
__device__ bf16 g_qh [4096L * 1024], g_ql [4096L * 1024];
__device__ bf16 g_kh [4096L * 1024], g_kl [4096L * 1024];
__device__ bf16 g_vh [4096L * 1024], g_vl [4096L * 1024];
__device__ bf16 g_oh [4096L * 1024], g_ol [4096L * 1024];
__device__ float g_sc[2048L * 2 * 16 * 2048];          // scores fp32 (s,b,h,t)
__device__ bf16 g_ah [2048L * 2 * 16 * 2048];          // attn hi
__device__ bf16 g_al [2048L * 2 * 16 * 2048];          // attn lo

// ---------------------------------------------------------------------------
// Helpers
// ---------------------------------------------------------------------------
__device__ __forceinline__ void mma16816(float* c, uint32_t a0, uint32_t a1,
                                         uint32_t a2, uint32_t a3,
                                         uint32_t b0, uint32_t b1)
{
    asm volatile(
        "mma.sync.aligned.m16n8k16.row.col.f32.bf16.bf16.f32 "
        "{%0,%1,%2,%3}, {%4,%5,%6,%7}, {%8,%9}, {%0,%1,%2,%3};"
        : "+f"(c[0]), "+f"(c[1]), "+f"(c[2]), "+f"(c[3])
        : "r"(a0), "r"(a1), "r"(a2), "r"(a3), "r"(b0), "r"(b1));
}

// split two floats into packed bf16 hi/lo pairs
__device__ __forceinline__ void split2(float x, float y, uint32_t& h, uint32_t& l)
{
    bf16 hx = __float2bfloat16(x), hy = __float2bfloat16(y);
    bf16 lx = __float2bfloat16(x - __bfloat162float(hx));
    bf16 ly = __float2bfloat16(y - __bfloat162float(hy));
    h = ((uint32_t)__bfloat16_as_ushort(hy) << 16) | __bfloat16_as_ushort(hx);
    l = ((uint32_t)__bfloat16_as_ushort(ly) << 16) | __bfloat16_as_ushort(lx);
}

// ---------------------------------------------------------------------------
// One-time fp32 -> bf16 hi/lo split of an array (vectorized by 4)
// ---------------------------------------------------------------------------
__global__ __launch_bounds__(256)
void split_f32(const float* __restrict__ s, bf16* __restrict__ hi,
               bf16* __restrict__ lo, int n4)
{
    int i = blockIdx.x * blockDim.x + threadIdx.x;
    if (i >= n4) return;
    float4 v = *(const float4*)(s + (long)i * 4);
    uint32_t h0, l0, h1, l1;
    split2(v.x, v.y, h0, l0);
    split2(v.z, v.w, h1, l1);
    *(uint2*)(hi + (long)i * 4) = make_uint2(h0, h1);
    *(uint2*)(lo + (long)i * 4) = make_uint2(l0, l1);
}

// ---------------------------------------------------------------------------
// NT GEMM body, pre-split bf16 operands, split-bf16 fp32 emulation.
// C = alpha * A*B^T (+bias). CTA 128x128, KC=32. 256 thr, 8 warps (2m x 4n).
// Output: fp32 (Cf) if Cf != nullptr, else split bf16 (Ch, Cl).
// ---------------------------------------------------------------------------
#define KC 32
#define KP 40   // padded k stride (elems); conflict-free fragment loads

__device__ __forceinline__ void gemm_bf16_nt(
    const bf16* __restrict__ Ah, const bf16* __restrict__ Al, long lda,
    const bf16* __restrict__ Bh, const bf16* __restrict__ Bl, long ldb,
    const float* __restrict__ bias, int K, float alpha,
    float* __restrict__ Cf, bf16* __restrict__ Ch, bf16* __restrict__ Cl,
    long ldc)
{
    __shared__ bf16 sAh[128 * KP], sAl[128 * KP];
    __shared__ bf16 sBh[128 * KP], sBl[128 * KP];

    const int tid  = threadIdx.x;
    const int wid  = tid >> 5;
    const int lane = tid & 31;
    const int wm   = (wid >> 2) * 64;
    const int wn   = (wid & 3) * 32;
    const int lrow = lane >> 2;
    const int lk2  = (lane & 3) * 2;

    float acc[4][4][4];
#pragma unroll
    for (int i = 0; i < 4; i++)
#pragma unroll
        for (int j = 0; j < 4; j++)
#pragma unroll
            for (int r = 0; r < 4; r++) acc[i][j][r] = 0.0f;

    for (int k0 = 0; k0 < K; k0 += KC) {
        // stage: 128 rows x 32 k per array, uint2 = 4 bf16; 4 iters x 4 arrays
#pragma unroll
        for (int i = 0; i < 4; i++) {
            int idx = tid + i * 256;
            int row = idx >> 3;
            int c4  = (idx & 7) * 4;
            *(uint2*)&sAh[row * KP + c4] = *(const uint2*)&Ah[(long)row * lda + k0 + c4];
            *(uint2*)&sAl[row * KP + c4] = *(const uint2*)&Al[(long)row * lda + k0 + c4];
            *(uint2*)&sBh[row * KP + c4] = *(const uint2*)&Bh[(long)row * ldb + k0 + c4];
            *(uint2*)&sBl[row * KP + c4] = *(const uint2*)&Bl[(long)row * ldb + k0 + c4];
        }
        __syncthreads();

#pragma unroll
        for (int kc = 0; kc < KC; kc += 16) {
            uint32_t bh[4][2], bl[4][2];
#pragma unroll
            for (int nt = 0; nt < 4; nt++) {
                int nrow = wn + nt * 8 + lrow;
                int kk   = kc + lk2;
                bh[nt][0] = *(const uint32_t*)&sBh[nrow * KP + kk];
                bh[nt][1] = *(const uint32_t*)&sBh[nrow * KP + kk + 8];
                bl[nt][0] = *(const uint32_t*)&sBl[nrow * KP + kk];
                bl[nt][1] = *(const uint32_t*)&sBl[nrow * KP + kk + 8];
            }
#pragma unroll
            for (int mt = 0; mt < 4; mt++) {
                int mrow = wm + mt * 16 + lrow;
                int kk   = kc + lk2;
                uint32_t ah0 = *(const uint32_t*)&sAh[mrow * KP + kk];
                uint32_t ah1 = *(const uint32_t*)&sAh[(mrow + 8) * KP + kk];
                uint32_t ah2 = *(const uint32_t*)&sAh[mrow * KP + kk + 8];
                uint32_t ah3 = *(const uint32_t*)&sAh[(mrow + 8) * KP + kk + 8];
                uint32_t al0 = *(const uint32_t*)&sAl[mrow * KP + kk];
                uint32_t al1 = *(const uint32_t*)&sAl[(mrow + 8) * KP + kk];
                uint32_t al2 = *(const uint32_t*)&sAl[mrow * KP + kk + 8];
                uint32_t al3 = *(const uint32_t*)&sAl[(mrow + 8) * KP + kk + 8];
#pragma unroll
                for (int nt = 0; nt < 4; nt++) {
                    mma16816(acc[mt][nt], ah0, ah1, ah2, ah3, bh[nt][0], bh[nt][1]);
                    mma16816(acc[mt][nt], ah0, ah1, ah2, ah3, bl[nt][0], bl[nt][1]);
                    mma16816(acc[mt][nt], al0, al1, al2, al3, bh[nt][0], bh[nt][1]);
                }
            }
        }
        __syncthreads();
    }

    // epilogue
#pragma unroll
    for (int mt = 0; mt < 4; mt++) {
        int row = wm + mt * 16 + lrow;
#pragma unroll
        for (int nt = 0; nt < 4; nt++) {
            int col = wn + nt * 8 + (lane & 3) * 2;
            float b0 = 0.f, b1 = 0.f;
            if (bias) { b0 = bias[col]; b1 = bias[col + 1]; }
            float y00 = acc[mt][nt][0] * alpha + b0;
            float y01 = acc[mt][nt][1] * alpha + b1;
            float y10 = acc[mt][nt][2] * alpha + b0;
            float y11 = acc[mt][nt][3] * alpha + b1;
            if (Cf) {
                *(float2*)(Cf + (long)row * ldc + col)       = make_float2(y00, y01);
                *(float2*)(Cf + (long)(row + 8) * ldc + col) = make_float2(y10, y11);
            } else {
                uint32_t h, l;
                split2(y00, y01, h, l);
                *(uint32_t*)&Ch[(long)row * ldc + col] = h;
                *(uint32_t*)&Cl[(long)row * ldc + col] = l;
                split2(y10, y11, h, l);
                *(uint32_t*)&Ch[(long)(row + 8) * ldc + col] = h;
                *(uint32_t*)&Cl[(long)(row + 8) * ldc + col] = l;
            }
        }
    }
}

// ---------------------------------------------------------------------------
// Wrappers
// ---------------------------------------------------------------------------
__global__ __launch_bounds__(256)
void gemm_qkv(const float* __restrict__ bq, const float* __restrict__ bk,
              const float* __restrict__ bv)
{
    const long bm = blockIdx.y, bn = blockIdx.x;
    const int  z  = blockIdx.z;
    const bf16* Wh = (z == 0) ? g_wqh : (z == 1) ? g_wkh : g_wvh;
    const bf16* Wl = (z == 0) ? g_wql : (z == 1) ? g_wkl : g_wvl;
    const float* b = (z == 0) ? bq   : (z == 1) ? bk   : bv;
    bf16* Ch = (z == 0) ? g_qh : (z == 1) ? g_kh : g_vh;
    bf16* Cl = (z == 0) ? g_ql : (z == 1) ? g_kl : g_vl;
    gemm_bf16_nt(g_xh + bm * 128 * 1024, g_xl + bm * 128 * 1024, 1024,
                 Wh + bn * 128 * 1024, Wl + bn * 128 * 1024, 1024,
                 b + bn * 128, 1024, 1.0f,
                 nullptr,
                 Ch + bm * 128 * 1024 + bn * 128,
                 Cl + bm * 128 * 1024 + bn * 128, 1024);
}

__global__ __launch_bounds__(256)
void gemm_sc()
{
    const long bm = blockIdx.y, bn = blockIdx.x, bz = blockIdx.z;  // bz = b*16+h
    gemm_bf16_nt(g_qh + bz * 64 + bm * 128 * 2048,
                 g_ql + bz * 64 + bm * 128 * 2048, 2048,
                 g_kh + bz * 64 + bn * 128 * 2048,
                 g_kl + bz * 64 + bn * 128 * 2048, 2048,
                 nullptr, 64, 0.125f,
                 g_sc + bz * 2048 + bm * 128 * 65536 + bn * 128,
                 nullptr, nullptr, 65536);
}

__global__ __launch_bounds__(256)
void gemm_proj(const float* __restrict__ bias, float* __restrict__ out)
{
    const long bm = blockIdx.y, bn = blockIdx.x;
    gemm_bf16_nt(g_oh + bm * 128 * 1024, g_ol + bm * 128 * 1024, 1024,
                 g_woh + bn * 128 * 1024, g_wol + bn * 128 * 1024, 1024,
                 bias + bn * 128, 1024, 1.0f,
                 out + bm * 128 * 1024 + bn * 128,
                 nullptr, nullptr, 1024);
}

// ---------------------------------------------------------------------------
// AV GEMM: O[s,d] = sum_t attn[s,t] * V[t,d]  per (b,h).
// NT form with B = V^T staged via smem transpose. CTA 128m x 64n, KC=32.
// 8 warps: 2m x 4n, warp tile 64 x 16 (4 mt x 2 nt). Split bf16 throughout.
// ---------------------------------------------------------------------------
__global__ __launch_bounds__(256)
void gemm_av()
{
    __shared__ bf16 sAh[128 * KP], sAl[128 * KP];
    __shared__ bf16 sBh[64 * KP],  sBl[64 * KP];

    const int tid  = threadIdx.x;
    const int wid  = tid >> 5;
    const int lane = tid & 31;
    const int wm   = (wid >> 2) * 64;
    const int wn   = (wid & 3) * 16;
    const int lrow = lane >> 2;
    const int lk2  = (lane & 3) * 2;

    const int  bz = blockIdx.z;          // b*16 + h
    const long m0 = blockIdx.y * 128;    // s-tile

    const long abase = (long)bz * 2048;  // attn: + s*65536 + t  (s-stride = B*H*T)
    const long vbase = (long)bz * 64;    // V: + t*2048 + d      (b*1024 + h*64 = 64*bz)
    const long obase = (long)bz * 64;    // O: + s*2048 + d

    float acc[4][2][4];
#pragma unroll
    for (int i = 0; i < 4; i++)
#pragma unroll
        for (int j = 0; j < 2; j++)
#pragma unroll
            for (int r = 0; r < 4; r++) acc[i][j][r] = 0.0f;

    for (int k0 = 0; k0 < T_; k0 += KC) {
        // stage attn tile: 128 s-rows x 32 t, hi and lo (s-stride 65536)
#pragma unroll
        for (int i = 0; i < 4; i++) {
            int idx = tid + i * 256;
            int row = idx >> 3;
            int c4  = (idx & 7) * 4;
            long ga = abase + (m0 + row) * 65536 + k0 + c4;
            *(uint2*)&sAh[row * KP + c4] = *(const uint2*)&g_ah[ga];
            *(uint2*)&sAl[row * KP + c4] = *(const uint2*)&g_al[ga];
        }
        // stage V^T: read V rows (t, 64 d), write sB[d][t]
        {
            int t  = tid >> 3;            // 0..31
            int d0 = (tid & 7) * 8;       // 0..56
            long gv = vbase + (long)(k0 + t) * 2048 + d0;
            uint4 hv = *(const uint4*)&g_vh[gv];
            uint4 lv = *(const uint4*)&g_vl[gv];
            const bf16* hp = (const bf16*)&hv;
            const bf16* lp = (const bf16*)&lv;
#pragma unroll
            for (int j = 0; j < 8; j++) {
                sBh[(d0 + j) * KP + t] = hp[j];
                sBl[(d0 + j) * KP + t] = lp[j];
            }
        }
        __syncthreads();

#pragma unroll
        for (int kc = 0; kc < KC; kc += 16) {
            uint32_t bh[2][2], bl[2][2];
#pragma unroll
            for (int nt = 0; nt < 2; nt++) {
                int nrow = wn + nt * 8 + lrow;
                int kk   = kc + lk2;
                bh[nt][0] = *(const uint32_t*)&sBh[nrow * KP + kk];
                bh[nt][1] = *(const uint32_t*)&sBh[nrow * KP + kk + 8];
                bl[nt][0] = *(const uint32_t*)&sBl[nrow * KP + kk];
                bl[nt][1] = *(const uint32_t*)&sBl[nrow * KP + kk + 8];
            }
#pragma unroll
            for (int mt = 0; mt < 4; mt++) {
                int mrow = wm + mt * 16 + lrow;
                int kk   = kc + lk2;
                uint32_t ah0 = *(const uint32_t*)&sAh[mrow * KP + kk];
                uint32_t ah1 = *(const uint32_t*)&sAh[(mrow + 8) * KP + kk];
                uint32_t ah2 = *(const uint32_t*)&sAh[mrow * KP + kk + 8];
                uint32_t ah3 = *(const uint32_t*)&sAh[(mrow + 8) * KP + kk + 8];
                uint32_t al0 = *(const uint32_t*)&sAl[mrow * KP + kk];
                uint32_t al1 = *(const uint32_t*)&sAl[(mrow + 8) * KP + kk];
                uint32_t al2 = *(const uint32_t*)&sAl[mrow * KP + kk + 8];
                uint32_t al3 = *(const uint32_t*)&sAl[(mrow + 8) * KP + kk + 8];
#pragma unroll
                for (int nt = 0; nt < 2; nt++) {
                    mma16816(acc[mt][nt], ah0, ah1, ah2, ah3, bh[nt][0], bh[nt][1]);
                    mma16816(acc[mt][nt], ah0, ah1, ah2, ah3, bl[nt][0], bl[nt][1]);
                    mma16816(acc[mt][nt], al0, al1, al2, al3, bh[nt][0], bh[nt][1]);
                }
            }
        }
        __syncthreads();
    }

    // epilogue: split to oh/ol; o offset = s*2048 + 64*bz + d
#pragma unroll
    for (int mt = 0; mt < 4; mt++) {
        long s = m0 + wm + mt * 16 + lrow;
#pragma unroll
        for (int nt = 0; nt < 2; nt++) {
            int col = wn + nt * 8 + (lane & 3) * 2;
            uint32_t h, l;
            split2(acc[mt][nt][0], acc[mt][nt][1], h, l);
            *(uint32_t*)&g_oh[s * 2048 + obase + col] = h;
            *(uint32_t*)&g_ol[s * 2048 + obase + col] = l;
            split2(acc[mt][nt][2], acc[mt][nt][3], h, l);
            *(uint32_t*)&g_oh[(s + 8) * 2048 + obase + col] = h;
            *(uint32_t*)&g_ol[(s + 8) * 2048 + obase + col] = l;
        }
    }
}

// ---------------------------------------------------------------------------
// Softmax over the HEAD axis; reads fp32 scores, writes split bf16 attn.
// ---------------------------------------------------------------------------
__global__ __launch_bounds__(256)
void softmax_split()
{
    long idx = (long)blockIdx.x * blockDim.x + threadIdx.x;
    const long total = (long)S_ * B_ * T_;
    if (idx >= total) return;

    int  t = (int)(idx % T_);
    long r = idx / T_;
    int  b = (int)(r % B_);
    long s = r / B_;
    long base = s * 65536 + (long)b * 32768 + t;

    float v[H_];
    float m = -1e30f;
#pragma unroll
    for (int h = 0; h < H_; h++) {
        v[h] = g_sc[base + (long)h * 2048];
        m = fmaxf(m, v[h]);
    }
    float sum = 0.0f;
#pragma unroll
    for (int h = 0; h < H_; h++) {
        v[h] = expf(v[h] - m);
        sum += v[h];
    }
    float inv = 1.0f / sum;
#pragma unroll
    for (int h = 0; h < H_; h++) {
        float a  = v[h] * inv;
        bf16 hh = __float2bfloat16(a);
        bf16 ll = __float2bfloat16(a - __bfloat162float(hh));
        g_ah[base + (long)h * 2048] = hh;
        g_al[base + (long)h * 2048] = ll;
    }
}

// ---------------------------------------------------------------------------
// Launch
// ---------------------------------------------------------------------------
extern "C" void kernel_launch(void* const* d_in, const int* in_sizes, int n_in,
                              void* d_out, int out_size)
{
    const float* x  = (const float*)d_in[0];
    const float* Wq = (const float*)d_in[1];
    const float* bq = (const float*)d_in[2];
    const float* Wk = (const float*)d_in[3];
    const float* bk = (const float*)d_in[4];
    const float* Wv = (const float*)d_in[5];
    const float* bv = (const float*)d_in[6];
    const float* Wo = (const float*)d_in[7];
    const float* bo = (const float*)d_in[8];
    float* out = (float*)d_out;

    bf16 *xh, *xl, *wqh, *wql, *wkh, *wkl, *wvh, *wvl, *woh, *wol;
    cudaGetSymbolAddress((void**)&xh,  g_xh);  cudaGetSymbolAddress((void**)&xl,  g_xl);
    cudaGetSymbolAddress((void**)&wqh, g_wqh); cudaGetSymbolAddress((void**)&wql, g_wql);
    cudaGetSymbolAddress((void**)&wkh, g_wkh); cudaGetSymbolAddress((void**)&wkl, g_wkl);
    cudaGetSymbolAddress((void**)&wvh, g_wvh); cudaGetSymbolAddress((void**)&wvl, g_wvl);
    cudaGetSymbolAddress((void**)&woh, g_woh); cudaGetSymbolAddress((void**)&wol, g_wol);

    // 0. one-time splits (x: 1M float4; W: 256K float4 each)
    split_f32<<<4096, 256>>>(x,  xh,  xl,  1048576);
    split_f32<<<1024, 256>>>(Wq, wqh, wql, 262144);
    split_f32<<<1024, 256>>>(Wk, wkh, wkl, 262144);
    split_f32<<<1024, 256>>>(Wv, wvh, wvl, 262144);
    split_f32<<<1024, 256>>>(Wo, woh, wol, 262144);

    // 1. Fused Q/K/V projections -> split bf16 q,k,v
    gemm_qkv<<<dim3(8, 32, 3), 256>>>(bq, bk, bv);

    // 2. scores -> fp32
    gemm_sc<<<dim3(16, 16, 32), 256>>>();

    // 3. softmax over heads -> split bf16 attn
    softmax_split<<<32768, 256>>>();

    // 4. O = attn @ V -> split bf16 o
    gemm_av<<<dim3(1, 16, 32), 256>>>();

    // 5. out projection -> fp32 output
    gemm_proj<<<dim3(8, 32, 1), 256>>>(bo, out);
}

// round 8
// speedup vs baseline: 2.2157x; 1.2383x over previous
#include <cuda_runtime.h>
#include <cuda_bf16.h>
#include <cstdint>

typedef __nv_bfloat16 bf16;

// Problem constants
#define S_  2048
#define B_  2
#define E_  1024
#define H_  16
#define D_  64
#define T_  2048

#define KC 32     // k elems per chunk
#define KP 40     // padded k stride (elems); 80B rows -> conflict-free ldmatrix

// ---------------------------------------------------------------------------
// Scratch (__device__ globals; no allocations allowed)
// ---------------------------------------------------------------------------
__device__ bf16 g_xh [4096L * 1024], g_xl [4096L * 1024];
__device__ bf16 g_wqh[1024L * 1024], g_wql[1024L * 1024];
__device__ bf16 g_wkh[1024L * 1024], g_wkl[1024L * 1024];
__device__ bf16 g_wvh[1024L * 1024], g_wvl[1024L * 1024];
__device__ bf16 g_woh[1024L * 1024], g_wol[1024L * 1024];
__device__ bf16 g_qh [4096L * 1024], g_ql [4096L * 1024];
__device__ bf16 g_kh [4096L * 1024], g_kl [4096L * 1024];
__device__ bf16 g_vh [4096L * 1024], g_vl [4096L * 1024];
__device__ bf16 g_vth[2048L * 2048], g_vtl[2048L * 2048];  // V^T per (b,h): row = bz*64+d
__device__ bf16 g_oh [4096L * 1024], g_ol [4096L * 1024];
__device__ float g_sc[2048L * 2 * 16 * 2048];              // scores fp32 (s,b,h,t)
__device__ bf16 g_ah [2048L * 2 * 16 * 2048];              // attn hi
__device__ bf16 g_al [2048L * 2 * 16 * 2048];              // attn lo

// ---------------------------------------------------------------------------
// Helpers
// ---------------------------------------------------------------------------
__device__ __forceinline__ uint32_t smem_u32(const void* p) {
    uint32_t a;
    asm("{ .reg .u64 t; cvta.to.shared.u64 t, %1; cvt.u32.u64 %0, t; }"
        : "=r"(a) : "l"(p));
    return a;
}

__device__ __forceinline__ void mma16816(float* c, uint32_t a0, uint32_t a1,
                                         uint32_t a2, uint32_t a3,
                                         uint32_t b0, uint32_t b1)
{
    asm volatile(
        "mma.sync.aligned.m16n8k16.row.col.f32.bf16.bf16.f32 "
        "{%0,%1,%2,%3}, {%4,%5,%6,%7}, {%8,%9}, {%0,%1,%2,%3};"
        : "+f"(c[0]), "+f"(c[1]), "+f"(c[2]), "+f"(c[3])
        : "r"(a0), "r"(a1), "r"(a2), "r"(a3), "r"(b0), "r"(b1));
}

__device__ __forceinline__ void ldsm4(uint32_t& d0, uint32_t& d1, uint32_t& d2,
                                      uint32_t& d3, uint32_t a)
{
    asm volatile("ldmatrix.sync.aligned.m8n8.x4.shared.b16 {%0,%1,%2,%3}, [%4];"
                 : "=r"(d0), "=r"(d1), "=r"(d2), "=r"(d3) : "r"(a));
}

__device__ __forceinline__ void cpa16(uint32_t dst, const void* src) {
    asm volatile("cp.async.cg.shared.global [%0], [%1], 16;" :: "r"(dst), "l"(src));
}
#define CP_COMMIT() asm volatile("cp.async.commit_group;" ::: "memory")
#define CP_WAIT(n)  asm volatile("cp.async.wait_group %0;" :: "n"(n) : "memory")

__device__ __forceinline__ void split2(float x, float y, uint32_t& h, uint32_t& l)
{
    bf16 hx = __float2bfloat16(x), hy = __float2bfloat16(y);
    bf16 lx = __float2bfloat16(x - __bfloat162float(hx));
    bf16 ly = __float2bfloat16(y - __bfloat162float(hy));
    h = ((uint32_t)__bfloat16_as_ushort(hy) << 16) | __bfloat16_as_ushort(hx);
    l = ((uint32_t)__bfloat16_as_ushort(ly) << 16) | __bfloat16_as_ushort(lx);
}

// ---------------------------------------------------------------------------
// One-time fp32 -> bf16 hi/lo split
// ---------------------------------------------------------------------------
__global__ __launch_bounds__(256)
void split_f32(const float* __restrict__ s, bf16* __restrict__ hi,
               bf16* __restrict__ lo, int n4)
{
    int i = blockIdx.x * blockDim.x + threadIdx.x;
    if (i >= n4) return;
    float4 v = *(const float4*)(s + (long)i * 4);
    uint32_t h0, l0, h1, l1;
    split2(v.x, v.y, h0, l0);
    split2(v.z, v.w, h1, l1);
    *(uint2*)(hi + (long)i * 4) = make_uint2(h0, h1);
    *(uint2*)(lo + (long)i * 4) = make_uint2(l0, l1);
}

// ---------------------------------------------------------------------------
// V^T precompute: g_vt[bz*64 + d][t] = g_v[t*2048 + bz*64 + d]
// grid (64 t-tiles, 32 bz), 256 threads, 32(t) x 64(d) smem tile.
// ---------------------------------------------------------------------------
__global__ __launch_bounds__(256)
void transpose_v()
{
    __shared__ bf16 th[32 * 68], tl[32 * 68];
    const int bz = blockIdx.y;
    const int t0 = blockIdx.x * 32;
    const int tid = threadIdx.x;

#pragma unroll
    for (int i = 0; i < 2; i++) {
        int id = tid + i * 256;          // 0..511
        int t  = id >> 4;                // 16 uint2 per t-row
        int d  = (id & 15) * 4;
        long g = (long)(t0 + t) * 2048 + (long)bz * 64 + d;
        *(uint2*)&th[t * 68 + d] = *(const uint2*)&g_vh[g];
        *(uint2*)&tl[t * 68 + d] = *(const uint2*)&g_vl[g];
    }
    __syncthreads();
#pragma unroll
    for (int i = 0; i < 2; i++) {
        int id = tid + i * 256;
        int d  = id >> 3;                // 0..63
        int t  = (id & 7) * 4;
        uint32_t h0 = ((uint32_t)__bfloat16_as_ushort(th[(t + 1) * 68 + d]) << 16)
                    | __bfloat16_as_ushort(th[(t + 0) * 68 + d]);
        uint32_t h1 = ((uint32_t)__bfloat16_as_ushort(th[(t + 3) * 68 + d]) << 16)
                    | __bfloat16_as_ushort(th[(t + 2) * 68 + d]);
        uint32_t l0 = ((uint32_t)__bfloat16_as_ushort(tl[(t + 1) * 68 + d]) << 16)
                    | __bfloat16_as_ushort(tl[(t + 0) * 68 + d]);
        uint32_t l1 = ((uint32_t)__bfloat16_as_ushort(tl[(t + 3) * 68 + d]) << 16)
                    | __bfloat16_as_ushort(tl[(t + 2) * 68 + d]);
        long o = (long)(bz * 64 + d) * 2048 + t0 + t;
        *(uint2*)&g_vth[o] = make_uint2(h0, h1);
        *(uint2*)&g_vtl[o] = make_uint2(l0, l1);
    }
}

// ---------------------------------------------------------------------------
// NT GEMM body: cp.async double-buffered, ldmatrix-fed, split-bf16 emulation.
// C = alpha*A*B^T (+bias). CTA 128x128, 256 thr = 8 warps (2m x 4n).
// Dynamic smem: 2 bufs x [Ah|Al|Bh|Bl] x 128*KP bf16 = 81920 B.
// ---------------------------------------------------------------------------
#define ARR_  10240u            // 128*KP*2 bytes
#define BUF_  40960u

__device__ __forceinline__ void gemm_bf16_nt(
    const bf16* __restrict__ Ah, const bf16* __restrict__ Al, long lda,
    const bf16* __restrict__ Bh, const bf16* __restrict__ Bl, long ldb,
    const float* __restrict__ bias, int K, float alpha,
    float* __restrict__ Cf, bf16* __restrict__ Ch, bf16* __restrict__ Cl,
    long ldc)
{
    extern __shared__ bf16 sm_[];
    const uint32_t sb = smem_u32(sm_);
    const int tid = threadIdx.x, wid = tid >> 5, lane = tid & 31;
    const int wm = (wid >> 2) * 64, wn = (wid & 3) * 32;

    // ldmatrix per-lane offsets (bytes) rel. to (row0, k0) of a tile
    const uint32_t aoff = (((lane & 15) * KP) + ((lane >> 4) * 8)) * 2;
    const uint32_t boff = ((((lane & 7) + ((lane >> 4) << 3)) * KP)
                           + (((lane >> 3) & 1) * 8)) * 2;

    float acc[4][4][4];
#pragma unroll
    for (int i = 0; i < 4; i++)
#pragma unroll
        for (int j = 0; j < 4; j++)
#pragma unroll
            for (int r = 0; r < 4; r++) acc[i][j][r] = 0.0f;

    const int nchunks = K / KC;

    // stage chunk k0 into buffer b
    auto stage = [&](int b, int k0) {
        uint32_t base = sb + (uint32_t)b * BUF_;
#pragma unroll
        for (int i = 0; i < 2; i++) {
            int id  = tid + i * 256;     // 0..511
            int row = id >> 2;           // 0..127
            int c8  = (id & 3) * 8;      // 0,8,16,24
            uint32_t so = (uint32_t)(row * KP + c8) * 2;
            cpa16(base + so,            Ah + (long)row * lda + k0 + c8);
            cpa16(base + ARR_ + so,     Al + (long)row * lda + k0 + c8);
            cpa16(base + 2 * ARR_ + so, Bh + (long)row * ldb + k0 + c8);
            cpa16(base + 3 * ARR_ + so, Bl + (long)row * ldb + k0 + c8);
        }
    };

    stage(0, 0);
    CP_COMMIT();

    for (int c = 0; c < nchunks; c++) {
        const int cur = c & 1;
        if (c + 1 < nchunks) {
            stage(cur ^ 1, (c + 1) * KC);
            CP_COMMIT();
            CP_WAIT(1);
        } else {
            CP_WAIT(0);
        }
        __syncthreads();

        const uint32_t bufb = sb + (uint32_t)cur * BUF_;
        const uint32_t abh = bufb + (uint32_t)wm * KP * 2 + aoff;
        const uint32_t abl = abh + ARR_;
        const uint32_t bbh = bufb + 2 * ARR_ + (uint32_t)wn * KP * 2 + boff;
        const uint32_t bbl = bbh + ARR_;

#pragma unroll
        for (int kc = 0; kc < 2; kc++) {
            const uint32_t ko = kc * 32;            // 16 elems = 32 B
            uint32_t BH[8], BL[8];
            ldsm4(BH[0], BH[1], BH[2], BH[3], bbh + ko);
            ldsm4(BH[4], BH[5], BH[6], BH[7], bbh + 16 * KP * 2 + ko);
            ldsm4(BL[0], BL[1], BL[2], BL[3], bbl + ko);
            ldsm4(BL[4], BL[5], BL[6], BL[7], bbl + 16 * KP * 2 + ko);
#pragma unroll
            for (int mt = 0; mt < 4; mt++) {
                uint32_t a0, a1, a2, a3, l0, l1, l2, l3;
                ldsm4(a0, a1, a2, a3, abh + (uint32_t)mt * 16 * KP * 2 + ko);
                ldsm4(l0, l1, l2, l3, abl + (uint32_t)mt * 16 * KP * 2 + ko);
#pragma unroll
                for (int nt = 0; nt < 4; nt++) {
                    mma16816(acc[mt][nt], a0, a1, a2, a3, BH[2 * nt], BH[2 * nt + 1]);
                    mma16816(acc[mt][nt], a0, a1, a2, a3, BL[2 * nt], BL[2 * nt + 1]);
                    mma16816(acc[mt][nt], l0, l1, l2, l3, BH[2 * nt], BH[2 * nt + 1]);
                }
            }
        }
        __syncthreads();
    }

    const int lrow = lane >> 2;
#pragma unroll
    for (int mt = 0; mt < 4; mt++) {
        int row = wm + mt * 16 + lrow;
#pragma unroll
        for (int nt = 0; nt < 4; nt++) {
            int col = wn + nt * 8 + (lane & 3) * 2;
            float b0 = 0.f, b1 = 0.f;
            if (bias) { b0 = bias[col]; b1 = bias[col + 1]; }
            float y00 = acc[mt][nt][0] * alpha + b0;
            float y01 = acc[mt][nt][1] * alpha + b1;
            float y10 = acc[mt][nt][2] * alpha + b0;
            float y11 = acc[mt][nt][3] * alpha + b1;
            if (Cf) {
                *(float2*)(Cf + (long)row * ldc + col)       = make_float2(y00, y01);
                *(float2*)(Cf + (long)(row + 8) * ldc + col) = make_float2(y10, y11);
            } else {
                uint32_t h, l;
                split2(y00, y01, h, l);
                *(uint32_t*)&Ch[(long)row * ldc + col] = h;
                *(uint32_t*)&Cl[(long)row * ldc + col] = l;
                split2(y10, y11, h, l);
                *(uint32_t*)&Ch[(long)(row + 8) * ldc + col] = h;
                *(uint32_t*)&Cl[(long)(row + 8) * ldc + col] = l;
            }
        }
    }
}

// ---------------------------------------------------------------------------
// Wrappers (dynamic smem = 81920)
// ---------------------------------------------------------------------------
__global__ __launch_bounds__(256)
void gemm_qkv(const float* __restrict__ bq, const float* __restrict__ bk,
              const float* __restrict__ bv)
{
    const long bm = blockIdx.y, bn = blockIdx.x;
    const int  z  = blockIdx.z;
    const bf16* Wh = (z == 0) ? g_wqh : (z == 1) ? g_wkh : g_wvh;
    const bf16* Wl = (z == 0) ? g_wql : (z == 1) ? g_wkl : g_wvl;
    const float* b = (z == 0) ? bq   : (z == 1) ? bk   : bv;
    bf16* Ch = (z == 0) ? g_qh : (z == 1) ? g_kh : g_vh;
    bf16* Cl = (z == 0) ? g_ql : (z == 1) ? g_kl : g_vl;
    gemm_bf16_nt(g_xh + bm * 128 * 1024, g_xl + bm * 128 * 1024, 1024,
                 Wh + bn * 128 * 1024, Wl + bn * 128 * 1024, 1024,
                 b + bn * 128, 1024, 1.0f,
                 nullptr,
                 Ch + bm * 128 * 1024 + bn * 128,
                 Cl + bm * 128 * 1024 + bn * 128, 1024);
}

__global__ __launch_bounds__(256)
void gemm_sc()
{
    const long bm = blockIdx.y, bn = blockIdx.x, bz = blockIdx.z;  // bz = b*16+h
    gemm_bf16_nt(g_qh + bz * 64 + bm * 128 * 2048,
                 g_ql + bz * 64 + bm * 128 * 2048, 2048,
                 g_kh + bz * 64 + bn * 128 * 2048,
                 g_kl + bz * 64 + bn * 128 * 2048, 2048,
                 nullptr, 64, 0.125f,
                 g_sc + bz * 2048 + bm * 128 * 65536 + bn * 128,
                 nullptr, nullptr, 65536);
}

__global__ __launch_bounds__(256)
void gemm_proj(const float* __restrict__ bias, float* __restrict__ out)
{
    const long bm = blockIdx.y, bn = blockIdx.x;
    gemm_bf16_nt(g_oh + bm * 128 * 1024, g_ol + bm * 128 * 1024, 1024,
                 g_woh + bn * 128 * 1024, g_wol + bn * 128 * 1024, 1024,
                 bias + bn * 128, 1024, 1.0f,
                 out + bm * 128 * 1024 + bn * 128,
                 nullptr, nullptr, 1024);
}

// ---------------------------------------------------------------------------
// AV GEMM: O = attn @ V using pre-transposed V^T (NT form).
// CTA 128m x 64n, 8 warps (2m x 4n), warp tile 64x16 (4mt x 2nt).
// Dynamic smem: 2 bufs x [Ah(10240)|Al(10240)|Bh(5120)|Bl(5120)] = 61440 B.
// ---------------------------------------------------------------------------
#define AV_ARR_A 10240u
#define AV_ARR_B 5120u
#define AV_BUF   30720u

__global__ __launch_bounds__(256)
void gemm_av()
{
    extern __shared__ bf16 sm_[];
    const uint32_t sb = smem_u32(sm_);
    const int tid = threadIdx.x, wid = tid >> 5, lane = tid & 31;
    const int wm = (wid >> 2) * 64, wn = (wid & 3) * 16;

    const int  bz = blockIdx.z;          // b*16 + h
    const long m0 = blockIdx.y * 128;    // s-tile

    const bf16* Ahp = g_ah + (long)bz * 2048;     // + s*65536 + t
    const bf16* Alp = g_al + (long)bz * 2048;
    const bf16* Bhp = g_vth + (long)bz * 64 * 2048;  // row d, ld 2048
    const bf16* Blp = g_vtl + (long)bz * 64 * 2048;

    const uint32_t aoff = (((lane & 15) * KP) + ((lane >> 4) * 8)) * 2;
    const uint32_t boff = ((((lane & 7) + ((lane >> 4) << 3)) * KP)
                           + (((lane >> 3) & 1) * 8)) * 2;

    float acc[4][2][4];
#pragma unroll
    for (int i = 0; i < 4; i++)
#pragma unroll
        for (int j = 0; j < 2; j++)
#pragma unroll
            for (int r = 0; r < 4; r++) acc[i][j][r] = 0.0f;

    auto stage = [&](int b, int k0) {
        uint32_t base = sb + (uint32_t)b * AV_BUF;
#pragma unroll
        for (int i = 0; i < 2; i++) {                 // A: 512 tasks per array
            int id  = tid + i * 256;
            int row = id >> 2;
            int c8  = (id & 3) * 8;
            uint32_t so = (uint32_t)(row * KP + c8) * 2;
            long ga = (m0 + row) * 65536 + k0 + c8;
            cpa16(base + so,            Ahp + ga);
            cpa16(base + AV_ARR_A + so, Alp + ga);
        }
        {                                             // B: 256 tasks per array
            int row = tid >> 2;                       // 0..63 (d)
            int c8  = (tid & 3) * 8;
            uint32_t so = (uint32_t)(row * KP + c8) * 2;
            long gb = (long)row * 2048 + k0 + c8;
            cpa16(base + 2 * AV_ARR_A + so,            Bhp + gb);
            cpa16(base + 2 * AV_ARR_A + AV_ARR_B + so, Blp + gb);
        }
    };

    stage(0, 0);
    CP_COMMIT();

    const int nchunks = T_ / KC;   // 64
    for (int c = 0; c < nchunks; c++) {
        const int cur = c & 1;
        if (c + 1 < nchunks) {
            stage(cur ^ 1, (c + 1) * KC);
            CP_COMMIT();
            CP_WAIT(1);
        } else {
            CP_WAIT(0);
        }
        __syncthreads();

        const uint32_t bufb = sb + (uint32_t)cur * AV_BUF;
        const uint32_t abh = bufb + (uint32_t)wm * KP * 2 + aoff;
        const uint32_t abl = abh + AV_ARR_A;
        const uint32_t bbh = bufb + 2 * AV_ARR_A + (uint32_t)wn * KP * 2 + boff;
        const uint32_t bbl = bbh + AV_ARR_B;

#pragma unroll
        for (int kc = 0; kc < 2; kc++) {
            const uint32_t ko = kc * 32;
            uint32_t BH[4], BL[4];
            ldsm4(BH[0], BH[1], BH[2], BH[3], bbh + ko);
            ldsm4(BL[0], BL[1], BL[2], BL[3], bbl + ko);
#pragma unroll
            for (int mt = 0; mt < 4; mt++) {
                uint32_t a0, a1, a2, a3, l0, l1, l2, l3;
                ldsm4(a0, a1, a2, a3, abh + (uint32_t)mt * 16 * KP * 2 + ko);
                ldsm4(l0, l1, l2, l3, abl + (uint32_t)mt * 16 * KP * 2 + ko);
#pragma unroll
                for (int nt = 0; nt < 2; nt++) {
                    mma16816(acc[mt][nt], a0, a1, a2, a3, BH[2 * nt], BH[2 * nt + 1]);
                    mma16816(acc[mt][nt], a0, a1, a2, a3, BL[2 * nt], BL[2 * nt + 1]);
                    mma16816(acc[mt][nt], l0, l1, l2, l3, BH[2 * nt], BH[2 * nt + 1]);
                }
            }
        }
        __syncthreads();
    }

    // epilogue: split to oh/ol; o offset = s*2048 + 64*bz + d
    const int lrow = lane >> 2;
    const long obase = (long)bz * 64;
#pragma unroll
    for (int mt = 0; mt < 4; mt++) {
        long s = m0 + wm + mt * 16 + lrow;
#pragma unroll
        for (int nt = 0; nt < 2; nt++) {
            int col = wn + nt * 8 + (lane & 3) * 2;
            uint32_t h, l;
            split2(acc[mt][nt][0], acc[mt][nt][1], h, l);
            *(uint32_t*)&g_oh[s * 2048 + obase + col] = h;
            *(uint32_t*)&g_ol[s * 2048 + obase + col] = l;
            split2(acc[mt][nt][2], acc[mt][nt][3], h, l);
            *(uint32_t*)&g_oh[(s + 8) * 2048 + obase + col] = h;
            *(uint32_t*)&g_ol[(s + 8) * 2048 + obase + col] = l;
        }
    }
}

// ---------------------------------------------------------------------------
// Softmax over the HEAD axis; float4-vectorized over t.
// ---------------------------------------------------------------------------
__global__ __launch_bounds__(256)
void softmax_split()
{
    long idx = (long)blockIdx.x * blockDim.x + threadIdx.x;   // 2097152 total
    int  t = (int)(idx & 511) * 4;
    long r = idx >> 9;
    int  b = (int)(r & 1);
    long s = r >> 1;
    long base = s * 65536 + (long)b * 32768 + t;

    float4 v[H_];
    float4 m = make_float4(-1e30f, -1e30f, -1e30f, -1e30f);
#pragma unroll
    for (int h = 0; h < H_; h++) {
        v[h] = *(const float4*)&g_sc[base + (long)h * 2048];
        m.x = fmaxf(m.x, v[h].x); m.y = fmaxf(m.y, v[h].y);
        m.z = fmaxf(m.z, v[h].z); m.w = fmaxf(m.w, v[h].w);
    }
    float4 sum = make_float4(0.f, 0.f, 0.f, 0.f);
#pragma unroll
    for (int h = 0; h < H_; h++) {
        v[h].x = expf(v[h].x - m.x); v[h].y = expf(v[h].y - m.y);
        v[h].z = expf(v[h].z - m.z); v[h].w = expf(v[h].w - m.w);
        sum.x += v[h].x; sum.y += v[h].y; sum.z += v[h].z; sum.w += v[h].w;
    }
    float4 inv = make_float4(1.f / sum.x, 1.f / sum.y, 1.f / sum.z, 1.f / sum.w);
#pragma unroll
    for (int h = 0; h < H_; h++) {
        float a0 = v[h].x * inv.x, a1 = v[h].y * inv.y;
        float a2 = v[h].z * inv.z, a3 = v[h].w * inv.w;
        uint32_t h0, l0, h1, l1;
        split2(a0, a1, h0, l0);
        split2(a2, a3, h1, l1);
        *(uint2*)&g_ah[base + (long)h * 2048] = make_uint2(h0, h1);
        *(uint2*)&g_al[base + (long)h * 2048] = make_uint2(l0, l1);
    }
}

// ---------------------------------------------------------------------------
// Launch
// ---------------------------------------------------------------------------
extern "C" void kernel_launch(void* const* d_in, const int* in_sizes, int n_in,
                              void* d_out, int out_size)
{
    const float* x  = (const float*)d_in[0];
    const float* Wq = (const float*)d_in[1];
    const float* bq = (const float*)d_in[2];
    const float* Wk = (const float*)d_in[3];
    const float* bk = (const float*)d_in[4];
    const float* Wv = (const float*)d_in[5];
    const float* bv = (const float*)d_in[6];
    const float* Wo = (const float*)d_in[7];
    const float* bo = (const float*)d_in[8];
    float* out = (float*)d_out;

    bf16 *xh, *xl, *wqh, *wql, *wkh, *wkl, *wvh, *wvl, *woh, *wol;
    cudaGetSymbolAddress((void**)&xh,  g_xh);  cudaGetSymbolAddress((void**)&xl,  g_xl);
    cudaGetSymbolAddress((void**)&wqh, g_wqh); cudaGetSymbolAddress((void**)&wql, g_wql);
    cudaGetSymbolAddress((void**)&wkh, g_wkh); cudaGetSymbolAddress((void**)&wkl, g_wkl);
    cudaGetSymbolAddress((void**)&wvh, g_wvh); cudaGetSymbolAddress((void**)&wvl, g_wvl);
    cudaGetSymbolAddress((void**)&woh, g_woh); cudaGetSymbolAddress((void**)&wol, g_wol);

    cudaFuncSetAttribute(gemm_qkv,  cudaFuncAttributeMaxDynamicSharedMemorySize, 81920);
    cudaFuncSetAttribute(gemm_sc,   cudaFuncAttributeMaxDynamicSharedMemorySize, 81920);
    cudaFuncSetAttribute(gemm_proj, cudaFuncAttributeMaxDynamicSharedMemorySize, 81920);
    cudaFuncSetAttribute(gemm_av,   cudaFuncAttributeMaxDynamicSharedMemorySize, 61440);

    // 0. one-time splits
    split_f32<<<4096, 256>>>(x,  xh,  xl,  1048576);
    split_f32<<<1024, 256>>>(Wq, wqh, wql, 262144);
    split_f32<<<1024, 256>>>(Wk, wkh, wkl, 262144);
    split_f32<<<1024, 256>>>(Wv, wvh, wvl, 262144);
    split_f32<<<1024, 256>>>(Wo, woh, wol, 262144);

    // 1. Fused Q/K/V projections
    gemm_qkv<<<dim3(8, 32, 3), 256, 81920>>>(bq, bk, bv);

    // 2. V^T precompute
    transpose_v<<<dim3(64, 32), 256>>>();

    // 3. scores -> fp32
    gemm_sc<<<dim3(16, 16, 32), 256, 81920>>>();

    // 4. softmax over heads -> split bf16 attn
    softmax_split<<<8192, 256>>>();

    // 5. O = attn @ V^T
    gemm_av<<<dim3(1, 16, 32), 256, 61440>>>();

    // 6. out projection -> fp32 output
    gemm_proj<<<dim3(8, 32, 1), 256, 81920>>>(bo, out);
}